// round 3
// baseline (speedup 1.0000x reference)
#include <cuda_runtime.h>
#include <cstdint>

// DerivNet2D fused kernel, round 1 design (3rd submission — rounds 1 and 2 hit
// GPU-broker capacity timeouts; no kernel ever executed): fp32 CUDA-core,
// fully fused.
//
// Math (per sample j, x = (x0, x1)):
//   h1_i  = w1[i,0]x0^2 + w1[i,1]x1^2 + w1_2[i,0]x0 + w1_2[i,1]x1 + b1[i]
//   z1    = tanh(h1),  s1 = 1 - z1^2
//   d1_i  = w1[i,0]x0 + w1_2[i,0],  d2_i = w1[i,1]x1 + w1_2[i,1]
//   A0_i  = z1^2, A1_i = z1*s1*d1, A2_i = z1*s1*d2
//   h2_m  = sum_i w2[m,i]A0_i + b2[m],  v1_m = sum_i w2[m,i]A1_i, v2 likewise
//   z2    = tanh(h2), s2 = 1 - z2^2
//   y_j   = sum_m w3[m] z2^2 + b3
//   g_kj  = sum_m 4 w3[m] z2 s2 v_k      (factor 2 from dh2dz1, 2 from dydz2)
// Output layout: out[0:NX)=y, out[NX:2NX)=dydx2=g2, out[2NX:3NX)=-dydx1=-g1

#define NXS     32768
#define NH      1024
#define MT      16          // samples per CTA
#define MC      256         // m per chunk
#define KC      32          // k per smem stage
#define THREADS 256
#define W2S_STRIDE 257      // pad: (k*257+m)%32 == (k+m)%32 -> conflict-free

// ---- packed fp32x2 helpers (FFMA2: 2x FFMA rate on sm_103a) ----
__device__ __forceinline__ unsigned long long pack_dup(float v) {
    unsigned long long r;
    asm("mov.b64 %0, {%1, %1};" : "=l"(r) : "f"(v));
    return r;
}
__device__ __forceinline__ void unpack2(unsigned long long v, float& lo, float& hi) {
    asm("mov.b64 {%0, %1}, %2;" : "=f"(lo), "=f"(hi) : "l"(v));
}
__device__ __forceinline__ void ffma2(unsigned long long& acc,
                                      unsigned long long a,
                                      unsigned long long b) {
    asm("fma.rn.f32x2 %0, %1, %2, %0;" : "+l"(acc) : "l"(a), "l"(b));
}

extern __shared__ float smem[];

__global__ void __launch_bounds__(THREADS, 1)
derivnet2d_fused_kernel(const float* __restrict__ x,
                        const float* __restrict__ w1,
                        const float* __restrict__ w1_2,
                        const float* __restrict__ b1,
                        const float* __restrict__ w2,
                        const float* __restrict__ b2,
                        const float* __restrict__ w3,
                        const float* __restrict__ b3,
                        float* __restrict__ out)
{
    // SMEM layout (floats):
    float* A0s = smem;                       // [NH][MT]   (k-major, j contiguous)
    float* A1s = A0s + NH * MT;
    float* A2s = A1s + NH * MT;
    float* w2s = A2s + NH * MT;              // [KC][W2S_STRIDE]
    float* xs  = w2s + KC * W2S_STRIDE;      // [MT*2]

    const int tid = threadIdx.x;
    const int blk = blockIdx.x;
    const int j0  = blk * MT;

    if (tid < MT * 2) xs[tid] = x[j0 * 2 + tid];
    __syncthreads();

    // ---------------- Phase 1: layer-1 features into SMEM ----------------
    for (int idx = tid; idx < MT * NH; idx += THREADS) {
        const int i = idx >> 4;   // feature 0..1023
        const int j = idx & 15;   // sample  0..15
        const float w10 = w1[2 * i],   w11 = w1[2 * i + 1];
        const float v10 = w1_2[2 * i], v11 = w1_2[2 * i + 1];
        const float x0 = xs[2 * j], x1 = xs[2 * j + 1];
        const float h = fmaf(w10, x0 * x0,
                        fmaf(w11, x1 * x1,
                        fmaf(v10, x0,
                        fmaf(v11, x1, b1[i]))));
        const float z  = tanhf(h);
        const float s  = 1.0f - z * z;
        const float d1 = fmaf(w10, x0, v10);
        const float d2 = fmaf(w11, x1, v11);
        const float zs = z * s;
        A0s[i * MT + j] = z * z;
        A1s[i * MT + j] = zs * d1;
        A2s[i * MT + j] = zs * d2;
    }
    // (visibility of A*s guaranteed by the __syncthreads() at the top of the
    //  first kc stage, which precedes any A*s read)

    const int jt = tid >> 7;    // 0..1  : which 8-sample half this thread covers
    const int mg = tid & 127;   // 0..127: m lane within chunk

    float yp[8], g1p[8], g2p[8];
#pragma unroll
    for (int jj = 0; jj < 8; ++jj) { yp[jj] = 0.f; g1p[jj] = 0.f; g2p[jj] = 0.f; }

    // ---------------- Phase 2: triple GEMM vs w2, fused epilogue ----------------
    for (int mc = 0; mc < NH / MC; ++mc) {          // 4 m-chunks
        const int m0 = mc * MC;

        unsigned long long acc0[2][4], acc1[2][4], acc2[2][4];
#pragma unroll
        for (int mm = 0; mm < 2; ++mm)
#pragma unroll
            for (int jp = 0; jp < 4; ++jp) {
                acc0[mm][jp] = 0ULL; acc1[mm][jp] = 0ULL; acc2[mm][jp] = 0ULL;
            }

        for (int kc = 0; kc < NH / KC; ++kc) {      // 32 k stages
            const int k0 = kc * KC;
            __syncthreads();
            // stage w2 tile transposed to k-major: w2s[k][m]
#pragma unroll
            for (int t = 0; t < (KC * MC) / THREADS; ++t) {
                const int idx = tid + t * THREADS;
                const int kl = idx & (KC - 1);
                const int ml = idx >> 5;
                w2s[kl * W2S_STRIDE + ml] = w2[(m0 + ml) * NH + (k0 + kl)];
            }
            __syncthreads();

#pragma unroll 8
            for (int k = 0; k < KC; ++k) {
                const int row = (k0 + k) * MT + jt * 8;
                // 8 samples -> 4 packed f32x2 per matrix (broadcast LDS within warp)
                const ulonglong2 q0a = *(const ulonglong2*)(A0s + row);
                const ulonglong2 q0b = *(const ulonglong2*)(A0s + row + 4);
                const ulonglong2 q1a = *(const ulonglong2*)(A1s + row);
                const ulonglong2 q1b = *(const ulonglong2*)(A1s + row + 4);
                const ulonglong2 q2a = *(const ulonglong2*)(A2s + row);
                const ulonglong2 q2b = *(const ulonglong2*)(A2s + row + 4);

                const float wA = w2s[k * W2S_STRIDE + mg];
                const float wB = w2s[k * W2S_STRIDE + mg + 128];
                const unsigned long long wdA = pack_dup(wA);
                const unsigned long long wdB = pack_dup(wB);

                ffma2(acc0[0][0], q0a.x, wdA); ffma2(acc0[0][1], q0a.y, wdA);
                ffma2(acc0[0][2], q0b.x, wdA); ffma2(acc0[0][3], q0b.y, wdA);
                ffma2(acc0[1][0], q0a.x, wdB); ffma2(acc0[1][1], q0a.y, wdB);
                ffma2(acc0[1][2], q0b.x, wdB); ffma2(acc0[1][3], q0b.y, wdB);

                ffma2(acc1[0][0], q1a.x, wdA); ffma2(acc1[0][1], q1a.y, wdA);
                ffma2(acc1[0][2], q1b.x, wdA); ffma2(acc1[0][3], q1b.y, wdA);
                ffma2(acc1[1][0], q1a.x, wdB); ffma2(acc1[1][1], q1a.y, wdB);
                ffma2(acc1[1][2], q1b.x, wdB); ffma2(acc1[1][3], q1b.y, wdB);

                ffma2(acc2[0][0], q2a.x, wdA); ffma2(acc2[0][1], q2a.y, wdA);
                ffma2(acc2[0][2], q2b.x, wdA); ffma2(acc2[0][3], q2b.y, wdA);
                ffma2(acc2[1][0], q2a.x, wdB); ffma2(acc2[1][1], q2a.y, wdB);
                ffma2(acc2[1][2], q2b.x, wdB); ffma2(acc2[1][3], q2b.y, wdB);
            }
        }

        // fused layer-2 nonlinearity + layer-3 partial reduction
#pragma unroll
        for (int mm = 0; mm < 2; ++mm) {
            const int m = m0 + mg + mm * 128;
            const float b2m = __ldg(&b2[m]);
            const float w3m = __ldg(&w3[m]);
#pragma unroll
            for (int jp = 0; jp < 4; ++jp) {
                float hlo, hhi, v1lo, v1hi, v2lo, v2hi;
                unpack2(acc0[mm][jp], hlo, hhi);
                unpack2(acc1[mm][jp], v1lo, v1hi);
                unpack2(acc2[mm][jp], v2lo, v2hi);
                {
                    const float z2 = tanhf(hlo + b2m);
                    const float s2 = 1.0f - z2 * z2;
                    yp[jp * 2]  = fmaf(w3m, z2 * z2, yp[jp * 2]);
                    const float c4 = 4.0f * w3m * z2 * s2;
                    g1p[jp * 2] = fmaf(c4, v1lo, g1p[jp * 2]);
                    g2p[jp * 2] = fmaf(c4, v2lo, g2p[jp * 2]);
                }
                {
                    const float z2 = tanhf(hhi + b2m);
                    const float s2 = 1.0f - z2 * z2;
                    yp[jp * 2 + 1]  = fmaf(w3m, z2 * z2, yp[jp * 2 + 1]);
                    const float c4 = 4.0f * w3m * z2 * s2;
                    g1p[jp * 2 + 1] = fmaf(c4, v1hi, g1p[jp * 2 + 1]);
                    g2p[jp * 2 + 1] = fmaf(c4, v2hi, g2p[jp * 2 + 1]);
                }
            }
        }
    }

    // ---------------- Final cross-thread reduction (reuse w2s) ----------------
    float* red = w2s;  // needs 16*128 floats, have 32*257
    const float b3v = b3[0];

    // y
    __syncthreads();
#pragma unroll
    for (int jj = 0; jj < 8; ++jj) red[(jt * 8 + jj) * 128 + mg] = yp[jj];
    __syncthreads();
    if (tid < MT) {
        float s = 0.f;
        for (int c = 0; c < 128; ++c) s += red[tid * 128 + c];
        out[j0 + tid] = s + b3v;
    }
    // dydx2 = g2
    __syncthreads();
#pragma unroll
    for (int jj = 0; jj < 8; ++jj) red[(jt * 8 + jj) * 128 + mg] = g2p[jj];
    __syncthreads();
    if (tid < MT) {
        float s = 0.f;
        for (int c = 0; c < 128; ++c) s += red[tid * 128 + c];
        out[NXS + j0 + tid] = s;
    }
    // -dydx1 = -g1
    __syncthreads();
#pragma unroll
    for (int jj = 0; jj < 8; ++jj) red[(jt * 8 + jj) * 128 + mg] = g1p[jj];
    __syncthreads();
    if (tid < MT) {
        float s = 0.f;
        for (int c = 0; c < 128; ++c) s += red[tid * 128 + c];
        out[2 * NXS + j0 + tid] = -s;
    }
}

extern "C" void kernel_launch(void* const* d_in, const int* in_sizes, int n_in,
                              void* d_out, int out_size) {
    const float* x    = (const float*)d_in[0];
    const float* w1   = (const float*)d_in[1];
    const float* w1_2 = (const float*)d_in[2];
    const float* b1   = (const float*)d_in[3];
    const float* w2   = (const float*)d_in[4];
    const float* b2   = (const float*)d_in[5];
    const float* w3   = (const float*)d_in[6];
    const float* b3   = (const float*)d_in[7];
    float* out = (float*)d_out;

    const size_t smem_bytes =
        (size_t)(3 * NH * MT + KC * W2S_STRIDE + MT * 2) * sizeof(float); // 229632
    cudaFuncSetAttribute(derivnet2d_fused_kernel,
                         cudaFuncAttributeMaxDynamicSharedMemorySize,
                         (int)smem_bytes);

    derivnet2d_fused_kernel<<<NXS / MT, THREADS, smem_bytes>>>(
        x, w1, w1_2, b1, w2, b2, w3, b3, out);
}

// round 13
// speedup vs baseline: 6.3672x; 6.3672x over previous
#include <cuda_runtime.h>
#include <cuda_fp16.h>
#include <cstdint>

// DerivNet2D round 13: mma.sync.m16n8k16 pipeline (tcgen05 rejected by the
// harness's compute_103 ptxas). Round-12 audit found + fixed a B-operand
// addressing bug (missing n0 warp-neuron offset). Never executed yet.
//  phase1a: layer-1 features -> fp16 scratch (pre-swizzled SW128 K-major tiles)
//  phase1b: w2 -> fp16 scratch (same tiling)
//  phase2 : triple GEMM (A0,A1,A2 vs shared w2), cp.async ring-3 pipeline,
//           ldmatrix + mma.sync, fused layer-2 tanh + layer-3 reduction.
// Output: out[0:NX)=y, out[NX:2NX)=dydx2, out[2NX:3NX)=-dydx1

#define NXS   32768
#define NH    1024
#define NKS   16             // k stages per full K (KC=64)
#define NMC   8              // m chunks of 128 neurons
#define NSTG  (NMC*NKS)      // 128 stages
#define TILEB 16384          // 128 rows x 128B scratch tile
#define RING  3
#define TPB   256

// phase-2 smem: stage = A0h,A1h,A2h (64x128B each) + B (128x128B) = 40960 B
#define STGB2   40960
#define SO2_B2  (RING*STGB2)            // 122880
#define SO2_W3  (SO2_B2 + 4096)        // 126976
#define SMEM_P2 131072

__device__ __align__(16) unsigned char g_Ascr[(size_t)256*16*3*TILEB]; // 192MB
__device__ __align__(16) unsigned char g_W2scr[(size_t)8*16*TILEB];    // 2MB

// ---------------- helpers ----------------
__device__ __forceinline__ uint32_t smem_u32(const void* p) {
    uint32_t a;
    asm("{ .reg .u64 t; cvta.to.shared.u64 t, %1; cvt.u32.u64 %0, t; }"
        : "=r"(a) : "l"(p));
    return a;
}
__device__ __forceinline__ uint32_t sw128(uint32_t b) { return b ^ ((b >> 3) & 0x70); }

__device__ __forceinline__ void cp16(uint32_t sdst, const void* gsrc) {
    asm volatile("cp.async.cg.shared.global [%0], [%1], 16;"
                 :: "r"(sdst), "l"(gsrc) : "memory");
}
#define CP_COMMIT() asm volatile("cp.async.commit_group;" ::: "memory")
#define CP_WAIT(n)  asm volatile("cp.async.wait_group %0;" :: "n"(n) : "memory")

__device__ __forceinline__ void ldsm_x4(uint32_t& r0, uint32_t& r1,
                                        uint32_t& r2, uint32_t& r3, uint32_t a) {
    asm volatile("ldmatrix.sync.aligned.m8n8.x4.shared.b16 {%0,%1,%2,%3}, [%4];"
                 : "=r"(r0), "=r"(r1), "=r"(r2), "=r"(r3) : "r"(a));
}
__device__ __forceinline__ void mma16816(float* d, uint32_t a0, uint32_t a1,
                                         uint32_t a2, uint32_t a3,
                                         uint32_t b0, uint32_t b1) {
    asm volatile("mma.sync.aligned.m16n8k16.row.col.f32.f16.f16.f32 "
                 "{%0,%1,%2,%3}, {%4,%5,%6,%7}, {%8,%9}, {%0,%1,%2,%3};"
                 : "+f"(d[0]), "+f"(d[1]), "+f"(d[2]), "+f"(d[3])
                 : "r"(a0), "r"(a1), "r"(a2), "r"(a3), "r"(b0), "r"(b1));
}

// Branch-free accurate tanh on the FMA pipe (no MUFU). abs err ~2e-7.
__device__ __forceinline__ float fast_tanh(float h) {
    float a = fminf(fabsf(h), 10.0f);
    float f = a * 2.8853900817779268f;           // 2*log2(e) -> exp(2a)=2^f
    float fm = f + 12582912.0f;
    int ib = __float_as_int(fm) & 0xFF;
    float fi = fm - 12582912.0f;
    float r = f - fi;
    float p = 1.5252733804059841e-05f;
    p = fmaf(p, r, 1.5403530393381610e-04f);
    p = fmaf(p, r, 1.3333558146428443e-03f);
    p = fmaf(p, r, 9.6181291076284772e-03f);
    p = fmaf(p, r, 5.5504108664821580e-02f);
    p = fmaf(p, r, 2.4022650695910071e-01f);
    p = fmaf(p, r, 6.9314718055994531e-01f);
    p = fmaf(p, r, 1.0f);
    float E = p * __int_as_float((ib + 127) << 23);  // exp(2a)
    float d = E + 1.0f;
    float y = __int_as_float(0x7EF311C3 - __float_as_int(d));
    y = y * fmaf(-d, y, 2.0f);
    y = y * fmaf(-d, y, 2.0f);
    y = y * fmaf(-d, y, 2.0f);
    float z = fmaf(-2.0f, y, 1.0f);
    return copysignf(z, h);
}

// ---------------- phase 1a: layer-1 features -> swizzled fp16 tiles ----------
__global__ void __launch_bounds__(TPB, 2)
phase1a(const float* __restrict__ x, const float* __restrict__ w1,
        const float* __restrict__ w1_2, const float* __restrict__ b1) {
    const int stile = blockIdx.x;        // 0..255 (128-sample tiles)
    const int ksq   = blockIdx.y;        // 0..3
    const int tid = threadIdx.x, wid = tid >> 5, lane = tid & 31;

    int   rprev = -1;
    float x0 = 0.f, x1 = 0.f;
    for (int u = wid; u < 128 * 4; u += 8) {
        const int r  = u >> 2;
        const int ks = ksq * 4 + (u & 3);
        if (r != rprev) {
            const int j = stile * 128 + r;
            x0 = __ldg(&x[2 * j]); x1 = __ldg(&x[2 * j + 1]);
            rprev = r;
        }
        const int i0 = ks * 64 + lane * 2;

        const float2 wa = __ldg((const float2*)w1 + i0);
        const float2 wb = __ldg((const float2*)w1 + i0 + 1);
        const float2 va = __ldg((const float2*)w1_2 + i0);
        const float2 vb = __ldg((const float2*)w1_2 + i0 + 1);
        const float ba = __ldg(&b1[i0]), bb = __ldg(&b1[i0 + 1]);

        float a0[2], a1[2], a2[2];
        {
            const float h = fmaf(wa.x, x0 * x0, fmaf(wa.y, x1 * x1,
                            fmaf(va.x, x0, fmaf(va.y, x1, ba))));
            const float z = fast_tanh(h), s = 1.0f - z * z;
            const float d1 = fmaf(wa.x, x0, va.x), d2 = fmaf(wa.y, x1, va.y);
            const float zs = z * s;
            a0[0] = z * z; a1[0] = zs * d1; a2[0] = zs * d2;
        }
        {
            const float h = fmaf(wb.x, x0 * x0, fmaf(wb.y, x1 * x1,
                            fmaf(vb.x, x0, fmaf(vb.y, x1, bb))));
            const float z = fast_tanh(h), s = 1.0f - z * z;
            const float d1 = fmaf(wb.x, x0, vb.x), d2 = fmaf(wb.y, x1, vb.y);
            const float zs = z * s;
            a0[1] = z * z; a1[1] = zs * d1; a2[1] = zs * d2;
        }
        const size_t tb = ((size_t)(stile * 16 + ks) * 3) * TILEB;
        const uint32_t off = sw128((uint32_t)(r * 128 + lane * 4));
        *(__half2*)(g_Ascr + tb + 0 * TILEB + off) = __floats2half2_rn(a0[0], a0[1]);
        *(__half2*)(g_Ascr + tb + 1 * TILEB + off) = __floats2half2_rn(a1[0], a1[1]);
        *(__half2*)(g_Ascr + tb + 2 * TILEB + off) = __floats2half2_rn(a2[0], a2[1]);
    }
}

// ---------------- phase 1b: w2 -> swizzled fp16 tiles ------------------------
__global__ void __launch_bounds__(TPB, 2)
phase1b(const float* __restrict__ w2) {
    const int t = blockIdx.x;            // 0..127 = mc*16+ks
    const int mc = t >> 4, ks = t & 15;
    for (int u = threadIdx.x; u < 128 * 32; u += TPB) {
        const int r = u >> 5, cp = (u & 31) * 2;
        const int m = mc * 128 + r, k = ks * 64 + cp;
        const float v0 = __ldg(&w2[m * NH + k]), v1 = __ldg(&w2[m * NH + k + 1]);
        const uint32_t off = sw128((uint32_t)(r * 128 + cp * 2));
        *(__half2*)(g_W2scr + (size_t)t * TILEB + off) = __floats2half2_rn(v0, v1);
    }
}

// ---------------- phase 2: triple GEMM via mma.sync + fused epilogue ---------
extern __shared__ unsigned char smem_raw[];

__global__ void __launch_bounds__(TPB, 1)
phase2(const float* __restrict__ b2, const float* __restrict__ w3,
       const float* __restrict__ b3, float* __restrict__ out) {
    const int cta  = blockIdx.x;         // 0..511 (64 samples each)
    const int stile = cta >> 1, hsel = cta & 1;
    const int tid = threadIdx.x, wid = tid >> 5, lane = tid & 31;
    const uint32_t sbase = smem_u32(smem_raw);
    float* b2s = (float*)(smem_raw + SO2_B2);
    float* w3s = (float*)(smem_raw + SO2_W3);

    for (int u = tid; u < NH; u += TPB) { b2s[u] = b2[u]; w3s[u] = w3[u]; }

    // warp tile: all 64 sample rows x 16 neuron cols (n0..n0+15) x 3 matrices
    const int n0 = wid * 16;
    const int g  = lane >> 2;            // fragment row group
    const int laneq = lane & 3;
    const int rA = lane & 15, segA = lane >> 4;                 // A ldmatrix map
    const int rB = (lane & 7) + ((lane >> 4) << 3);             // B ldmatrix map
    const int segB = (lane >> 3) & 1;

    float acc[3][4][2][4];               // [mat][mtile(16)][ntile(8)][frag]
    float yp[8], g1p[8], g2p[8];
#pragma unroll
    for (int i = 0; i < 8; ++i) { yp[i] = 0.f; g1p[i] = 0.f; g2p[i] = 0.f; }

    auto load_stage = [&](int s) {
        const int mc = s >> 4, ks = s & 15;
        const size_t abase = ((size_t)(stile * 16 + ks) * 3) * TILEB
                           + (size_t)hsel * 8192;
        const size_t bbase = (size_t)(mc * 16 + ks) * TILEB;
        const uint32_t sd = sbase + (uint32_t)(s % RING) * STGB2;
#pragma unroll
        for (int t = 0; t < 10; ++t) {
            const int idx = tid + t * TPB;          // 0..2559
            if (idx < 1536) {
                const int mat = idx >> 9;
                const uint32_t off = (uint32_t)(idx & 511) * 16;
                cp16(sd + mat * 8192 + off,
                     g_Ascr + abase + (size_t)mat * TILEB + off);
            } else {
                const uint32_t off = (uint32_t)(idx - 1536) * 16;
                cp16(sd + 24576 + off, g_W2scr + bbase + off);
            }
        }
        CP_COMMIT();
    };

    // prologue
    load_stage(0);
    load_stage(1);
    int s_load = 2;

    for (int mc = 0; mc < NMC; ++mc) {
#pragma unroll
        for (int mat = 0; mat < 3; ++mat)
#pragma unroll
            for (int mt = 0; mt < 4; ++mt)
#pragma unroll
                for (int nt = 0; nt < 2; ++nt)
#pragma unroll
                    for (int e = 0; e < 4; ++e) acc[mat][mt][nt][e] = 0.f;

        for (int ks = 0; ks < NKS; ++ks) {
            const int s = mc * NKS + ks;
            __syncthreads();                 // everyone done with slot (s-1)%RING
            if (s_load < NSTG) { load_stage(s_load); ++s_load; }
            {
                const int rem = NSTG - 1 - s;
                if (rem >= 2)      { CP_WAIT(2); }
                else if (rem == 1) { CP_WAIT(1); }
                else               { CP_WAIT(0); }
            }
            __syncthreads();                 // stage s visible to all warps

            const uint32_t sd = sbase + (uint32_t)(s % RING) * STGB2;
            const uint32_t Bb = sd + 24576;
#pragma unroll
            for (int kk = 0; kk < 4; ++kk) {
                uint32_t b0, b1, b2r, b3r;
                {
                    // FIX (round 13): include the warp's neuron offset n0.
                    const int nrow = n0 + rB;
                    const uint32_t nib = (uint32_t)(kk * 2 + segB);
                    const uint32_t a = Bb + (uint32_t)nrow * 128
                                     + ((nib ^ ((uint32_t)nrow & 7)) << 4);
                    ldsm_x4(b0, b1, b2r, b3r, a);
                }
#pragma unroll
                for (int mat = 0; mat < 3; ++mat) {
                    const uint32_t Ab = sd + mat * 8192;
#pragma unroll
                    for (int mt = 0; mt < 4; ++mt) {
                        uint32_t a0, a1, a2, a3;
                        const int row = mt * 16 + rA;
                        const uint32_t nib = (uint32_t)(kk * 2 + segA);
                        const uint32_t ad = Ab + (uint32_t)row * 128
                                          + ((nib ^ ((uint32_t)row & 7)) << 4);
                        ldsm_x4(a0, a1, a2, a3, ad);
                        mma16816(acc[mat][mt][0], a0, a1, a2, a3, b0, b1);
                        mma16816(acc[mat][mt][1], a0, a1, a2, a3, b2r, b3r);
                    }
                }
            }
        }

        // fused epilogue for this 128-neuron chunk
#pragma unroll
        for (int mt = 0; mt < 4; ++mt)
#pragma unroll
            for (int nt = 0; nt < 2; ++nt)
#pragma unroll
                for (int e = 0; e < 4; ++e) {
                    const int q = mc * 128 + n0 + nt * 8 + laneq * 2 + (e & 1);
                    const float h = acc[0][mt][nt][e] + b2s[q];
                    const float z = fast_tanh(h);
                    const float s2 = 1.0f - z * z;
                    const float w3m = w3s[q];
                    const int rs = mt * 2 + (e >> 1);
                    yp[rs] = fmaf(w3m, z * z, yp[rs]);
                    const float c4 = 4.0f * w3m * z * s2;
                    g1p[rs] = fmaf(c4, acc[1][mt][nt][e], g1p[rs]);
                    g2p[rs] = fmaf(c4, acc[2][mt][nt][e], g2p[rs]);
                }
    }

    // intra-warp reduction over the 4 neuron-column lanes of each quad
#pragma unroll
    for (int rs = 0; rs < 8; ++rs) {
        yp[rs]  += __shfl_xor_sync(0xFFFFFFFFu, yp[rs], 1);
        yp[rs]  += __shfl_xor_sync(0xFFFFFFFFu, yp[rs], 2);
        g1p[rs] += __shfl_xor_sync(0xFFFFFFFFu, g1p[rs], 1);
        g1p[rs] += __shfl_xor_sync(0xFFFFFFFFu, g1p[rs], 2);
        g2p[rs] += __shfl_xor_sync(0xFFFFFFFFu, g2p[rs], 1);
        g2p[rs] += __shfl_xor_sync(0xFFFFFFFFu, g2p[rs], 2);
    }

    // cross-warp reduction in smem (stage area is free now)
    float* red = (float*)smem_raw;       // [3][64][8] floats = 6KB (slot 0 area)
    __syncthreads();
    if (laneq == 0) {
#pragma unroll
        for (int rs = 0; rs < 8; ++rs) {
            const int row = (rs >> 1) * 16 + g + (rs & 1) * 8;
            red[0 * 512 + row * 8 + wid] = yp[rs];
            red[1 * 512 + row * 8 + wid] = g1p[rs];
            red[2 * 512 + row * 8 + wid] = g2p[rs];
        }
    }
    __syncthreads();
    if (tid < 64) {
        const int row = tid;
        float y = 0.f, g1 = 0.f, g2 = 0.f;
#pragma unroll
        for (int w = 0; w < 8; ++w) {
            y  += red[0 * 512 + row * 8 + w];
            g1 += red[1 * 512 + row * 8 + w];
            g2 += red[2 * 512 + row * 8 + w];
        }
        const int j = cta * 64 + row;
        out[j]           = y + b3[0];
        out[NXS + j]     = g2;
        out[2 * NXS + j] = -g1;
    }
}

// ---------------- launch -----------------------------------------------------
extern "C" void kernel_launch(void* const* d_in, const int* in_sizes, int n_in,
                              void* d_out, int out_size) {
    const float* x    = (const float*)d_in[0];
    const float* w1   = (const float*)d_in[1];
    const float* w1_2 = (const float*)d_in[2];
    const float* b1   = (const float*)d_in[3];
    const float* w2   = (const float*)d_in[4];
    const float* b2   = (const float*)d_in[5];
    const float* w3   = (const float*)d_in[6];
    const float* b3   = (const float*)d_in[7];
    float* out = (float*)d_out;

    cudaFuncSetAttribute(phase2, cudaFuncAttributeMaxDynamicSharedMemorySize,
                         SMEM_P2);

    phase1b<<<128, TPB>>>(w2);
    phase1a<<<dim3(256, 4), TPB>>>(x, w1, w1_2, b1);
    phase2<<<512, TPB, SMEM_P2>>>(b2, w3, b3, out);
}